// round 1
// baseline (speedup 1.0000x reference)
#include <cuda_runtime.h>
#include <cuda_bf16.h>

// GINConv forward: out = (segment_sum over CSR of X[column_index]) @ W
// X: [100000, 64] f32, W: [64, 64] f32, row_pointers: [100001] i32,
// column_index: [1.6M] i32. out: [100000, 64] f32.
//
// Fused warp-per-node kernel:
//  - each warp aggregates one node's neighbor rows (float2 per lane, 4-way
//    unrolled independent accumulators for MLP),
//  - W staged in smem once per block,
//  - per-node 64x64 GEMM via smem broadcast + conflict-free float2 W reads,
//  - coalesced float2 store.

#define D_FEAT 64
#define WARPS_PER_BLOCK 8

__global__ __launch_bounds__(256, 4) void gin_fused_kernel(
    const float* __restrict__ X,
    const float* __restrict__ W,
    const int*   __restrict__ rp,
    const int*   __restrict__ ci,
    float*       __restrict__ out,
    int n_nodes)
{
    __shared__ float Ws[D_FEAT * D_FEAT];          // 16 KB
    __shared__ float accS[WARPS_PER_BLOCK][D_FEAT]; // 2 KB

    const int tid  = threadIdx.x;
    const int wid  = tid >> 5;
    const int lane = tid & 31;

    // Stage W into smem (float4, 256 threads x 4 iters)
    #pragma unroll
    for (int k = tid; k < D_FEAT * D_FEAT / 4; k += 256) {
        reinterpret_cast<float4*>(Ws)[k] =
            reinterpret_cast<const float4*>(W)[k];
    }
    __syncthreads();

    const int node = blockIdx.x * WARPS_PER_BLOCK + wid;
    if (node >= n_nodes) return;

    const int start = __ldg(&rp[node]);
    const int end   = __ldg(&rp[node + 1]);

    const float2* __restrict__ Xv = reinterpret_cast<const float2*>(X);

    float2 a0 = make_float2(0.f, 0.f);
    float2 a1 = make_float2(0.f, 0.f);
    float2 a2 = make_float2(0.f, 0.f);
    float2 a3 = make_float2(0.f, 0.f);

    int e = start;
    // 4-way unroll: 4 independent gathers in flight per warp
    for (; e + 4 <= end; e += 4) {
        const int c0 = __ldg(&ci[e + 0]);
        const int c1 = __ldg(&ci[e + 1]);
        const int c2 = __ldg(&ci[e + 2]);
        const int c3 = __ldg(&ci[e + 3]);
        const float2 v0 = __ldg(&Xv[(size_t)c0 * 32 + lane]);
        const float2 v1 = __ldg(&Xv[(size_t)c1 * 32 + lane]);
        const float2 v2 = __ldg(&Xv[(size_t)c2 * 32 + lane]);
        const float2 v3 = __ldg(&Xv[(size_t)c3 * 32 + lane]);
        a0.x += v0.x; a0.y += v0.y;
        a1.x += v1.x; a1.y += v1.y;
        a2.x += v2.x; a2.y += v2.y;
        a3.x += v3.x; a3.y += v3.y;
    }
    for (; e < end; ++e) {
        const int c = __ldg(&ci[e]);
        const float2 v = __ldg(&Xv[(size_t)c * 32 + lane]);
        a0.x += v.x; a0.y += v.y;
    }

    float2 acc;
    acc.x = (a0.x + a1.x) + (a2.x + a3.x);
    acc.y = (a0.y + a1.y) + (a2.y + a3.y);

    // Stage aggregated row into smem for the per-node GEMM
    accS[wid][2 * lane + 0] = acc.x;
    accS[wid][2 * lane + 1] = acc.y;
    __syncwarp();

    // out[node][2*lane + {0,1}] = sum_k accS[wid][k] * W[k][2*lane + {0,1}]
    float o0 = 0.f, o1 = 0.f;
    #pragma unroll
    for (int k = 0; k < D_FEAT; ++k) {
        const float a = accS[wid][k];                       // smem broadcast
        const float2 w =
            reinterpret_cast<const float2*>(Ws + k * D_FEAT)[lane]; // conflict-free
        o0 = fmaf(a, w.x, o0);
        o1 = fmaf(a, w.y, o1);
    }

    reinterpret_cast<float2*>(out)[(size_t)node * 32 + lane] =
        make_float2(o0, o1);
}

extern "C" void kernel_launch(void* const* d_in, const int* in_sizes, int n_in,
                              void* d_out, int out_size) {
    const float* X  = (const float*)d_in[0];   // [100000, 64]
    const float* W  = (const float*)d_in[1];   // [64, 64]
    const int*   rp = (const int*)d_in[2];     // [100001]
    const int*   ci = (const int*)d_in[3];     // [1600000]
    float* out = (float*)d_out;                // [100000, 64]

    const int n_nodes = in_sizes[2] - 1;       // 100000
    const int blocks = (n_nodes + WARPS_PER_BLOCK - 1) / WARPS_PER_BLOCK;

    gin_fused_kernel<<<blocks, 256>>>(X, W, rp, ci, out, n_nodes);
}